// round 1
// baseline (speedup 1.0000x reference)
#include <cuda_runtime.h>
#include <cuda_bf16.h>
#include <cstdint>
#include <cstddef>

// Problem constants
#define MM   8192      // B*T tokens
#define DD   1024      // model dim
#define HH   8         // heads
#define HD   128       // head dim
#define SS   512       // sub-keys per half
#define KK   16        // top-k

// ---------------------------------------------------------------------------
// Scratch (static device globals; allocation-free per harness rules)
// ---------------------------------------------------------------------------
__device__ float g_h[(size_t)MM * DD];                 // 32 MB  hidden
__device__ float g_scores[(size_t)MM * HH * 2 * SS];   // 268 MB scores [m][h][a512|b512]
__device__ float g_merged[(size_t)MM * DD];            // 32 MB  expert output
__device__ float g_proj[(size_t)MM * DD];              // 32 MB  pre-LN projection

// ---------------------------------------------------------------------------
// Generic fp32 NT GEMM body: C[m][n] = sum_k A[m][k] * B[n][k]
// Block tile 128x128, K-tile 16, 256 threads, 8x8 per-thread micro-tile.
// All dims assumed divisible by tiles (true for every launch here).
// ---------------------------------------------------------------------------
__device__ __forceinline__ void sgemm_body(const float* __restrict__ A,
                                           const float* __restrict__ B,
                                           float* __restrict__ C,
                                           int Kdim, int lda, int ldb, int ldc)
{
    __shared__ float As[16][128];
    __shared__ float Bs[16][128];

    const int tid   = threadIdx.x;          // 0..255
    const int tx    = tid & 15;             // n-direction
    const int ty    = tid >> 4;             // m-direction
    const int row_m = blockIdx.y * 128;
    const int col_n = blockIdx.x * 128;

    float acc[8][8];
#pragma unroll
    for (int i = 0; i < 8; i++)
#pragma unroll
        for (int j = 0; j < 8; j++) acc[i][j] = 0.f;

    for (int k0 = 0; k0 < Kdim; k0 += 16) {
        // cooperative load: tile = 128 rows x 16 k = 512 float4; 2 per thread
#pragma unroll
        for (int i = 0; i < 2; i++) {
            int f  = tid * 2 + i;           // 0..511
            int r  = f >> 2;                // 0..127
            int kq = (f & 3) * 4;           // 0,4,8,12
            float4 va = *(const float4*)(A + (size_t)(row_m + r) * lda + k0 + kq);
            As[kq + 0][r] = va.x; As[kq + 1][r] = va.y;
            As[kq + 2][r] = va.z; As[kq + 3][r] = va.w;
            float4 vb = *(const float4*)(B + (size_t)(col_n + r) * ldb + k0 + kq);
            Bs[kq + 0][r] = vb.x; Bs[kq + 1][r] = vb.y;
            Bs[kq + 2][r] = vb.z; Bs[kq + 3][r] = vb.w;
        }
        __syncthreads();

#pragma unroll
        for (int kk = 0; kk < 16; kk++) {
            float a[8], b[8];
#pragma unroll
            for (int i = 0; i < 8; i++) a[i] = As[kk][ty * 8 + i];
#pragma unroll
            for (int j = 0; j < 8; j++) b[j] = Bs[kk][tx * 8 + j];
#pragma unroll
            for (int i = 0; i < 8; i++)
#pragma unroll
                for (int j = 0; j < 8; j++) acc[i][j] += a[i] * b[j];
        }
        __syncthreads();
    }

#pragma unroll
    for (int i = 0; i < 8; i++) {
        int m = row_m + ty * 8 + i;
#pragma unroll
        for (int j0 = 0; j0 < 8; j0 += 4) {
            float4 v = make_float4(acc[i][j0], acc[i][j0 + 1], acc[i][j0 + 2], acc[i][j0 + 3]);
            *(float4*)(C + (size_t)m * ldc + col_n + tx * 8 + j0) = v;
        }
    }
}

// GEMM1: g_h = x @ W_in^T
__global__ void __launch_bounds__(256) k_gemm_in(const float* __restrict__ x,
                                                 const float* __restrict__ Win)
{
    sgemm_body(x, Win, g_h, DD, DD, DD, DD);
}

// Score GEMMs: z = head*2 + ab. scores[m][head][ab*512+s] = h_head[m] . keys[head][s]
__global__ void __launch_bounds__(256) k_gemm_scores(const float* __restrict__ ka,
                                                     const float* __restrict__ kb)
{
    int z    = blockIdx.z;
    int head = z >> 1;
    int ab   = z & 1;
    const float* A = g_h + head * HD;                            // lda = DD
    const float* B = (ab ? kb : ka) + (size_t)head * SS * HD;    // ldb = HD
    float* C = g_scores + head * (2 * SS) + ab * SS;             // ldc = HH*2*SS
    sgemm_body(A, B, C, HD, DD, HD, HH * 2 * SS);
}

// GEMM2: g_proj = g_merged @ W_out^T
__global__ void __launch_bounds__(256) k_gemm_out(const float* __restrict__ Wout)
{
    sgemm_body(g_merged, Wout, g_proj, DD, DD, DD, DD);
}

// ---------------------------------------------------------------------------
// PEER selection + gather kernel: one warp per (token, head).
// Top-k via iterative warp argmax; all lists distributed one-entry-per-lane
// (no smem, no dynamic register indexing).
// ---------------------------------------------------------------------------
#define NEG_INF (-3.402823466e38f)

#define LOCAL_BEST(arr, n, bv, bi)                                   \
    {                                                                \
        bv = NEG_INF; bi = lane;                                     \
        _Pragma("unroll")                                            \
        for (int _j = 0; _j < (n); _j++) {                           \
            if ((arr)[_j] > bv) { bv = (arr)[_j]; bi = _j * 32 + lane; } \
        }                                                            \
    }

#define KILL(arr, n, gi)                                             \
    {                                                                \
        _Pragma("unroll")                                            \
        for (int _j = 0; _j < (n); _j++) {                           \
            if (_j == ((gi) >> 5)) (arr)[_j] = NEG_INF;              \
        }                                                            \
    }

#define WARP_ARGMAX(v, i)                                            \
    {                                                                \
        _Pragma("unroll")                                            \
        for (int _o = 16; _o; _o >>= 1) {                            \
            float _ov = __shfl_xor_sync(0xffffffffu, v, _o);         \
            int   _oi = __shfl_xor_sync(0xffffffffu, i, _o);         \
            if (_ov > v || (_ov == v && _oi < i)) { v = _ov; i = _oi; } \
        }                                                            \
    }

__global__ void __launch_bounds__(256) peer_kernel(const float* __restrict__ u_shared,
                                                   const float* __restrict__ expert_v)
{
    const int lane = threadIdx.x & 31;
    const int wid  = threadIdx.x >> 5;
    const int id   = blockIdx.x * 8 + wid;   // 0..65535 = m*H + head
    const int m    = id >> 3;
    const int head = id & 7;

    const float* srow = g_scores + (size_t)id * (2 * SS);

    // lane owns scores at indices j*32+lane
    float sa[16], sb[16];
#pragma unroll
    for (int j = 0; j < 16; j++) sa[j] = srow[j * 32 + lane];
#pragma unroll
    for (int j = 0; j < 16; j++) sb[j] = srow[SS + j * 32 + lane];

    // lane k holds the k-th top entry after each stage
    float ta_v = 0.f, tb_v = 0.f;
    int   ta_i = 0,   tb_i = 0;

    // ---- top-16 of scores_a ----
    for (int k = 0; k < 16; k++) {
        float bv; int bi;
        LOCAL_BEST(sa, 16, bv, bi);
        WARP_ARGMAX(bv, bi);
        if (lane == k) { ta_v = bv; ta_i = bi; }
        if ((bi & 31) == lane) KILL(sa, 16, bi);
    }
    // ---- top-16 of scores_b ----
    for (int k = 0; k < 16; k++) {
        float bv; int bi;
        LOCAL_BEST(sb, 16, bv, bi);
        WARP_ARGMAX(bv, bi);
        if (lane == k) { tb_v = bv; tb_i = bi; }
        if ((bi & 31) == lane) KILL(sb, 16, bi);
    }

    // ---- product scores: combo c = j*32+lane; ia = c>>4, ib = c&15 ----
    const int hi = (lane >> 4) & 1;
    const float tbv_mine = __shfl_sync(0xffffffffu, tb_v, lane & 15);
    float pv[8];
#pragma unroll
    for (int j = 0; j < 8; j++)
        pv[j] = __shfl_sync(0xffffffffu, ta_v, 2 * j + hi) + tbv_mine;

    // ---- top-16 of 256 product scores ----
    float sel_sc = 0.f; int sel_e = 0;
    for (int k = 0; k < 16; k++) {
        float bv; int bi;
        LOCAL_BEST(pv, 8, bv, bi);
        WARP_ARGMAX(bv, bi);
        int ia = bi >> 4, ib = bi & 15;
        int ei = __shfl_sync(0xffffffffu, ta_i, ia) * SS +
                 __shfl_sync(0xffffffffu, tb_i, ib);
        if (lane == k) { sel_sc = bv; sel_e = ei; }
        if ((bi & 31) == lane) KILL(pv, 8, bi);
    }

    // ---- softmax over the 16 selected scores (lane k holds k-th) ----
    const float mx = __shfl_sync(0xffffffffu, sel_sc, 0);  // first pick is the max
    float e   = (lane < 16) ? expf(sel_sc - mx) : 0.f;
    float sum = e;
#pragma unroll
    for (int o = 16; o; o >>= 1) sum += __shfl_xor_sync(0xffffffffu, sum, o);
    const float wgt = e / sum;

    // ---- gather expert vectors + weighted combine (lane owns 4 dims) ----
    float4 acc = make_float4(0.f, 0.f, 0.f, 0.f);
    const float4* ev4 = (const float4*)expert_v;
#pragma unroll
    for (int k = 0; k < 16; k++) {
        float wk = __shfl_sync(0xffffffffu, wgt, k);
        int   ek = __shfl_sync(0xffffffffu, sel_e, k);
        float4 v = ev4[(size_t)ek * 32 + lane];
        acc.x += wk * v.x; acc.y += wk * v.y; acc.z += wk * v.z; acc.w += wk * v.w;
    }

    // ---- shared-trunk activation: sigmoid(u . h_head) ----
    const float4 hv = ((const float4*)(g_h + (size_t)m * DD + head * HD))[lane];
    const float4 uv = ((const float4*)u_shared)[lane];
    float dot = hv.x * uv.x + hv.y * uv.y + hv.z * uv.z + hv.w * uv.w;
#pragma unroll
    for (int o = 16; o; o >>= 1) dot += __shfl_xor_sync(0xffffffffu, dot, o);
    const float act = 1.f / (1.f + expf(-dot));

    float4 o4 = make_float4(act * acc.x, act * acc.y, act * acc.z, act * acc.w);
    ((float4*)(g_merged + (size_t)m * DD + head * HD))[lane] = o4;
}

// ---------------------------------------------------------------------------
// LayerNorm over D=1024: one block (256 thr) per token, float4 per thread.
// ---------------------------------------------------------------------------
__device__ __forceinline__ float wsum(float v)
{
#pragma unroll
    for (int o = 16; o; o >>= 1) v += __shfl_xor_sync(0xffffffffu, v, o);
    return v;
}

__global__ void __launch_bounds__(256) ln_kernel(const float* __restrict__ ln_w,
                                                 const float* __restrict__ ln_b,
                                                 float* __restrict__ out)
{
    const int m    = blockIdx.x;
    const int tid  = threadIdx.x;
    const int lane = tid & 31;
    const int wid  = tid >> 5;

    const float4 v = ((const float4*)(g_proj + (size_t)m * DD))[tid];
    __shared__ float red[8];

    float s = v.x + v.y + v.z + v.w;
    s = wsum(s);
    if (lane == 0) red[wid] = s;
    __syncthreads();
    float mu;
    {
        float t = (lane < 8) ? red[lane] : 0.f;
        t = wsum(t);
        mu = t * (1.0f / 1024.0f);
    }
    __syncthreads();

    const float dx = v.x - mu, dy = v.y - mu, dz = v.z - mu, dw = v.w - mu;
    float q = dx * dx + dy * dy + dz * dz + dw * dw;
    q = wsum(q);
    if (lane == 0) red[wid] = q;
    __syncthreads();
    float var;
    {
        float t = (lane < 8) ? red[lane] : 0.f;
        t = wsum(t);
        var = t * (1.0f / 1024.0f);
    }
    const float inv = rsqrtf(var + 1e-5f);

    const float4 w4 = ((const float4*)ln_w)[tid];
    const float4 b4 = ((const float4*)ln_b)[tid];
    float4 o;
    o.x = dx * inv * w4.x + b4.x;
    o.y = dy * inv * w4.y + b4.y;
    o.z = dz * inv * w4.z + b4.z;
    o.w = dw * inv * w4.w + b4.w;
    ((float4*)(out + (size_t)m * DD))[tid] = o;
}

// ---------------------------------------------------------------------------
// Launch pipeline (all default stream; graph-capturable, allocation-free)
// ---------------------------------------------------------------------------
extern "C" void kernel_launch(void* const* d_in, const int* in_sizes, int n_in,
                              void* d_out, int out_size)
{
    (void)in_sizes; (void)n_in; (void)out_size;
    const float* x    = (const float*)d_in[0];
    const float* Win  = (const float*)d_in[1];
    const float* ka   = (const float*)d_in[2];
    const float* kb   = (const float*)d_in[3];
    const float* u    = (const float*)d_in[4];
    const float* ev   = (const float*)d_in[5];
    const float* Wout = (const float*)d_in[6];
    const float* lnw  = (const float*)d_in[7];
    const float* lnb  = (const float*)d_in[8];
    float* out = (float*)d_out;

    dim3 blk(256);
    k_gemm_in<<<dim3(DD / 128, MM / 128), blk>>>(x, Win);
    k_gemm_scores<<<dim3(SS / 128, MM / 128, HH * 2), blk>>>(ka, kb);
    peer_kernel<<<(MM * HH) / 8, blk>>>(u, ev);
    k_gemm_out<<<dim3(DD / 128, MM / 128), blk>>>(Wout);
    ln_kernel<<<MM, blk>>>(lnw, lnb, out);
}

// round 10
// speedup vs baseline: 1.0758x; 1.0758x over previous
#include <cuda_runtime.h>
#include <cuda_bf16.h>
#include <cstdint>
#include <cstddef>

// Problem constants
#define MM   8192      // B*T tokens
#define DD   1024      // model dim
#define HH   8         // heads
#define HD   128       // head dim
#define SS   512       // sub-keys per half
#define KK   16        // top-k

// ---------------------------------------------------------------------------
// Scratch (static device globals)
// ---------------------------------------------------------------------------
__device__ float g_h[(size_t)MM * DD];                 // hidden (fp32, = R1)
__device__ float g_scores[(size_t)MM * HH * 2 * SS];   // scores (fp32, = R1)
__device__ float g_merged[(size_t)MM * DD];            // expert output
__device__ float g_proj[(size_t)MM * DD];              // pre-LN projection

// ---------------------------------------------------------------------------
// fp32 NT SGEMM — EXACT R1 code (passed at 3.1e-7, 1947 us total).
// C[m][n] = sum_k A[m][k]*B[n][k]. Block 128x128, K-tile 16, 256 thr.
// ---------------------------------------------------------------------------
__device__ __forceinline__ void sgemm_body(const float* __restrict__ A,
                                           const float* __restrict__ B,
                                           float* __restrict__ C,
                                           int Kdim, int lda, int ldb, int ldc)
{
    __shared__ float As[16][128];
    __shared__ float Bs[16][128];

    const int tid   = threadIdx.x;
    const int tx    = tid & 15;
    const int ty    = tid >> 4;
    const int row_m = blockIdx.y * 128;
    const int col_n = blockIdx.x * 128;

    float acc[8][8];
#pragma unroll
    for (int i = 0; i < 8; i++)
#pragma unroll
        for (int j = 0; j < 8; j++) acc[i][j] = 0.f;

    for (int k0 = 0; k0 < Kdim; k0 += 16) {
#pragma unroll
        for (int i = 0; i < 2; i++) {
            int f  = tid * 2 + i;
            int r  = f >> 2;
            int kq = (f & 3) * 4;
            float4 va = *(const float4*)(A + (size_t)(row_m + r) * lda + k0 + kq);
            As[kq + 0][r] = va.x; As[kq + 1][r] = va.y;
            As[kq + 2][r] = va.z; As[kq + 3][r] = va.w;
            float4 vb = *(const float4*)(B + (size_t)(col_n + r) * ldb + k0 + kq);
            Bs[kq + 0][r] = vb.x; Bs[kq + 1][r] = vb.y;
            Bs[kq + 2][r] = vb.z; Bs[kq + 3][r] = vb.w;
        }
        __syncthreads();

#pragma unroll
        for (int kk = 0; kk < 16; kk++) {
            float a[8], b[8];
#pragma unroll
            for (int i = 0; i < 8; i++) a[i] = As[kk][ty * 8 + i];
#pragma unroll
            for (int j = 0; j < 8; j++) b[j] = Bs[kk][tx * 8 + j];
#pragma unroll
            for (int i = 0; i < 8; i++)
#pragma unroll
                for (int j = 0; j < 8; j++) acc[i][j] += a[i] * b[j];
        }
        __syncthreads();
    }

#pragma unroll
    for (int i = 0; i < 8; i++) {
        int m = row_m + ty * 8 + i;
#pragma unroll
        for (int j0 = 0; j0 < 8; j0 += 4) {
            float4 v = make_float4(acc[i][j0], acc[i][j0 + 1], acc[i][j0 + 2], acc[i][j0 + 3]);
            *(float4*)(C + (size_t)m * ldc + col_n + tx * 8 + j0) = v;
        }
    }
}

// GEMM1 (fp32, = R1): g_h = x @ W_in^T
__global__ void __launch_bounds__(256) k_gemm_in(const float* __restrict__ x,
                                                 const float* __restrict__ Win)
{
    sgemm_body(x, Win, g_h, DD, DD, DD, DD);
}

// Score GEMMs (fp32, = R1): z = head*2+ab
__global__ void __launch_bounds__(256) k_gemm_scores(const float* __restrict__ ka,
                                                     const float* __restrict__ kb)
{
    const int z = blockIdx.z;
    const int head = z >> 1;
    const int ab = z & 1;
    const float* A = g_h + head * HD;
    const float* B = (ab ? kb : ka) + (size_t)head * SS * HD;
    float* C = g_scores + head * (2 * SS) + ab * SS;
    sgemm_body(A, B, C, HD, DD, HD, HH * 2 * SS);
}

// ---------------------------------------------------------------------------
// tf32x3 mma.sync GEMM — certified fp32-equivalent for GEMM2 by the R5/R6
// A/B test (output delta 5e-9). Ran to completion in the R5 bench.
// Used ONLY for GEMM2.
// ---------------------------------------------------------------------------
__device__ __forceinline__ uint32_t to_tf32(float x) {
    uint32_t h;
    asm("cvt.rna.tf32.f32 %0, %1;" : "=r"(h) : "f"(x));
    return h;
}
__device__ __forceinline__ void split_tf32(float x, uint32_t& hi, uint32_t& lo) {
    hi = to_tf32(x);
    lo = to_tf32(x - __uint_as_float(hi));
}
__device__ __forceinline__ void mma_tf32(float* c, const uint32_t* a, const uint32_t* b) {
    asm volatile(
        "mma.sync.aligned.m16n8k8.row.col.f32.tf32.tf32.f32 "
        "{%0,%1,%2,%3}, {%4,%5,%6,%7}, {%8,%9}, {%0,%1,%2,%3};"
        : "+f"(c[0]), "+f"(c[1]), "+f"(c[2]), "+f"(c[3])
        : "r"(a[0]), "r"(a[1]), "r"(a[2]), "r"(a[3]), "r"(b[0]), "r"(b[1]));
}

#define SMEM_STRIDE 36

__device__ __forceinline__ void gemm_x3(const float* __restrict__ A,
                                        const float* __restrict__ B,
                                        float* __restrict__ C,
                                        int lda, int ldb, int ldc, int Kdim)
{
    __shared__ float As[128][SMEM_STRIDE];
    __shared__ float Bs[128][SMEM_STRIDE];

    const int tid  = threadIdx.x;
    const int lane = tid & 31;
    const int wid  = tid >> 5;
    const int wr   = wid >> 1;
    const int wc   = wid & 1;
    const int row_m = blockIdx.y * 128;
    const int col_n = blockIdx.x * 128;

    const int lr = lane >> 2;
    const int lc = lane & 3;

    float acc[2][8][4];
#pragma unroll
    for (int mt = 0; mt < 2; mt++)
#pragma unroll
        for (int nt = 0; nt < 8; nt++)
#pragma unroll
            for (int i = 0; i < 4; i++) acc[mt][nt][i] = 0.f;

    for (int k0 = 0; k0 < Kdim; k0 += 32) {
        __syncthreads();
#pragma unroll
        for (int i = 0; i < 4; i++) {
            const int f  = tid + i * 256;
            const int r  = f >> 3;
            const int c4 = (f & 7) * 4;
            *(float4*)&As[r][c4] = *(const float4*)(A + (size_t)(row_m + r) * lda + k0 + c4);
            *(float4*)&Bs[r][c4] = *(const float4*)(B + (size_t)(col_n + r) * ldb + k0 + c4);
        }
        __syncthreads();

#pragma unroll
        for (int ks = 0; ks < 4; ks++) {
            const int kk = ks * 8;
            uint32_t ah[2][4], al[2][4];
#pragma unroll
            for (int mt = 0; mt < 2; mt++) {
                const int rbase = 32 * wr + 16 * mt + lr;
                split_tf32(As[rbase    ][kk + lc    ], ah[mt][0], al[mt][0]);
                split_tf32(As[rbase + 8][kk + lc    ], ah[mt][1], al[mt][1]);
                split_tf32(As[rbase    ][kk + lc + 4], ah[mt][2], al[mt][2]);
                split_tf32(As[rbase + 8][kk + lc + 4], ah[mt][3], al[mt][3]);
            }
#pragma unroll
            for (int half = 0; half < 2; half++) {
                uint32_t bh[4][2], bl[4][2];
#pragma unroll
                for (int nt2 = 0; nt2 < 4; nt2++) {
                    const int n = 64 * wc + 8 * (half * 4 + nt2) + lr;
                    split_tf32(Bs[n][kk + lc    ], bh[nt2][0], bl[nt2][0]);
                    split_tf32(Bs[n][kk + lc + 4], bh[nt2][1], bl[nt2][1]);
                }
#pragma unroll
                for (int mt = 0; mt < 2; mt++)
#pragma unroll
                    for (int nt2 = 0; nt2 < 4; nt2++) {
                        float* c = acc[mt][half * 4 + nt2];
                        mma_tf32(c, ah[mt], bh[nt2]);   // hi*hi
                        mma_tf32(c, ah[mt], bl[nt2]);   // hi*lo
                        mma_tf32(c, al[mt], bh[nt2]);   // lo*hi
                    }
            }
        }
    }

#pragma unroll
    for (int mt = 0; mt < 2; mt++) {
        const int row0 = row_m + 32 * wr + 16 * mt + lr;
#pragma unroll
        for (int nt = 0; nt < 8; nt++) {
            const int col0 = col_n + 64 * wc + 8 * nt + 2 * lc;
            *(float2*)(C + (size_t)row0 * ldc + col0) =
                make_float2(acc[mt][nt][0], acc[mt][nt][1]);
            *(float2*)(C + (size_t)(row0 + 8) * ldc + col0) =
                make_float2(acc[mt][nt][2], acc[mt][nt][3]);
        }
    }
}

// GEMM2 (x3, certified): g_proj = g_merged @ W_out^T
__global__ void __launch_bounds__(256, 2) k_gemm_out(const float* __restrict__ Wout)
{
    gemm_x3(g_merged, Wout, g_proj, DD, DD, DD, DD);
}

// ---------------------------------------------------------------------------
// PEER selection + gather kernel — EXACT R1 code (passed at 3.1e-7).
// ---------------------------------------------------------------------------
#define NEG_INF (-3.402823466e38f)

#define LOCAL_BEST(arr, n, bv, bi)                                   \
    {                                                                \
        bv = NEG_INF; bi = lane;                                     \
        _Pragma("unroll")                                            \
        for (int _j = 0; _j < (n); _j++) {                           \
            if ((arr)[_j] > bv) { bv = (arr)[_j]; bi = _j * 32 + lane; } \
        }                                                            \
    }

#define KILL(arr, n, gi)                                             \
    {                                                                \
        _Pragma("unroll")                                            \
        for (int _j = 0; _j < (n); _j++) {                           \
            if (_j == ((gi) >> 5)) (arr)[_j] = NEG_INF;              \
        }                                                            \
    }

#define WARP_ARGMAX(v, i)                                            \
    {                                                                \
        _Pragma("unroll")                                            \
        for (int _o = 16; _o; _o >>= 1) {                            \
            float _ov = __shfl_xor_sync(0xffffffffu, v, _o);         \
            int   _oi = __shfl_xor_sync(0xffffffffu, i, _o);         \
            if (_ov > v || (_ov == v && _oi < i)) { v = _ov; i = _oi; } \
        }                                                            \
    }

__global__ void __launch_bounds__(256) peer_kernel(const float* __restrict__ u_shared,
                                                   const float* __restrict__ expert_v)
{
    const int lane = threadIdx.x & 31;
    const int wid  = threadIdx.x >> 5;
    const int id   = blockIdx.x * 8 + wid;   // m*H + head
    const int m    = id >> 3;
    const int head = id & 7;

    const float* srow = g_scores + (size_t)id * (2 * SS);

    float sa[16], sb[16];
#pragma unroll
    for (int j = 0; j < 16; j++) sa[j] = srow[j * 32 + lane];
#pragma unroll
    for (int j = 0; j < 16; j++) sb[j] = srow[SS + j * 32 + lane];

    float ta_v = 0.f, tb_v = 0.f;
    int   ta_i = 0,   tb_i = 0;

    for (int k = 0; k < 16; k++) {
        float bv; int bi;
        LOCAL_BEST(sa, 16, bv, bi);
        WARP_ARGMAX(bv, bi);
        if (lane == k) { ta_v = bv; ta_i = bi; }
        if ((bi & 31) == lane) KILL(sa, 16, bi);
    }
    for (int k = 0; k < 16; k++) {
        float bv; int bi;
        LOCAL_BEST(sb, 16, bv, bi);
        WARP_ARGMAX(bv, bi);
        if (lane == k) { tb_v = bv; tb_i = bi; }
        if ((bi & 31) == lane) KILL(sb, 16, bi);
    }

    const int hi = (lane >> 4) & 1;
    const float tbv_mine = __shfl_sync(0xffffffffu, tb_v, lane & 15);
    float pv[8];
#pragma unroll
    for (int j = 0; j < 8; j++)
        pv[j] = __shfl_sync(0xffffffffu, ta_v, 2 * j + hi) + tbv_mine;

    float sel_sc = 0.f; int sel_e = 0;
    for (int k = 0; k < 16; k++) {
        float bv; int bi;
        LOCAL_BEST(pv, 8, bv, bi);
        WARP_ARGMAX(bv, bi);
        int ia = bi >> 4, ib = bi & 15;
        int ei = __shfl_sync(0xffffffffu, ta_i, ia) * SS +
                 __shfl_sync(0xffffffffu, tb_i, ib);
        if (lane == k) { sel_sc = bv; sel_e = ei; }
        if ((bi & 31) == lane) KILL(pv, 8, bi);
    }

    const float mx = __shfl_sync(0xffffffffu, sel_sc, 0);
    float e   = (lane < 16) ? expf(sel_sc - mx) : 0.f;
    float sum = e;
#pragma unroll
    for (int o = 16; o; o >>= 1) sum += __shfl_xor_sync(0xffffffffu, sum, o);
    const float wgt = e / sum;

    float4 acc = make_float4(0.f, 0.f, 0.f, 0.f);
    const float4* ev4 = (const float4*)expert_v;
#pragma unroll
    for (int k = 0; k < 16; k++) {
        float wk = __shfl_sync(0xffffffffu, wgt, k);
        int   ek = __shfl_sync(0xffffffffu, sel_e, k);
        float4 v = ev4[(size_t)ek * 32 + lane];
        acc.x += wk * v.x; acc.y += wk * v.y; acc.z += wk * v.z; acc.w += wk * v.w;
    }

    const float4 hv = ((const float4*)(g_h + (size_t)m * DD + head * HD))[lane];
    const float4 uv = ((const float4*)u_shared)[lane];
    float dot = hv.x * uv.x + hv.y * uv.y + hv.z * uv.z + hv.w * uv.w;
#pragma unroll
    for (int o = 16; o; o >>= 1) dot += __shfl_xor_sync(0xffffffffu, dot, o);
    const float act = 1.f / (1.f + expf(-dot));

    float4 o4 = make_float4(act * acc.x, act * acc.y, act * acc.z, act * acc.w);
    ((float4*)(g_merged + (size_t)m * DD + head * HD))[lane] = o4;
}

// ---------------------------------------------------------------------------
// LayerNorm over D=1024: one block (256 thr) per token — EXACT R1 code
// ---------------------------------------------------------------------------
__device__ __forceinline__ float wsum(float v)
{
#pragma unroll
    for (int o = 16; o; o >>= 1) v += __shfl_xor_sync(0xffffffffu, v, o);
    return v;
}

__global__ void __launch_bounds__(256) ln_kernel(const float* __restrict__ ln_w,
                                                 const float* __restrict__ ln_b,
                                                 float* __restrict__ out)
{
    const int m    = blockIdx.x;
    const int tid  = threadIdx.x;
    const int lane = tid & 31;
    const int wid  = tid >> 5;

    const float4 v = ((const float4*)(g_proj + (size_t)m * DD))[tid];
    __shared__ float red[8];

    float s = v.x + v.y + v.z + v.w;
    s = wsum(s);
    if (lane == 0) red[wid] = s;
    __syncthreads();
    float mu;
    {
        float t = (lane < 8) ? red[lane] : 0.f;
        t = wsum(t);
        mu = t * (1.0f / 1024.0f);
    }
    __syncthreads();

    const float dx = v.x - mu, dy = v.y - mu, dz = v.z - mu, dw = v.w - mu;
    float q = dx * dx + dy * dy + dz * dz + dw * dw;
    q = wsum(q);
    if (lane == 0) red[wid] = q;
    __syncthreads();
    float var;
    {
        float t = (lane < 8) ? red[lane] : 0.f;
        t = wsum(t);
        var = t * (1.0f / 1024.0f);
    }
    const float inv = rsqrtf(var + 1e-5f);

    const float4 w4 = ((const float4*)ln_w)[tid];
    const float4 b4 = ((const float4*)ln_b)[tid];
    float4 o;
    o.x = dx * inv * w4.x + b4.x;
    o.y = dy * inv * w4.y + b4.y;
    o.z = dz * inv * w4.z + b4.z;
    o.w = dw * inv * w4.w + b4.w;
    ((float4*)(out + (size_t)m * DD))[tid] = o;
}

// ---------------------------------------------------------------------------
// Launch pipeline
// ---------------------------------------------------------------------------
extern "C" void kernel_launch(void* const* d_in, const int* in_sizes, int n_in,
                              void* d_out, int out_size)
{
    (void)in_sizes; (void)n_in; (void)out_size;
    const float* x    = (const float*)d_in[0];
    const float* Win  = (const float*)d_in[1];
    const float* ka   = (const float*)d_in[2];
    const float* kb   = (const float*)d_in[3];
    const float* u    = (const float*)d_in[4];
    const float* ev   = (const float*)d_in[5];
    const float* Wout = (const float*)d_in[6];
    const float* lnw  = (const float*)d_in[7];
    const float* lnb  = (const float*)d_in[8];
    float* out = (float*)d_out;

    dim3 blk(256);
    k_gemm_in<<<dim3(DD / 128, MM / 128), blk>>>(x, Win);
    k_gemm_scores<<<dim3(SS / 128, MM / 128, HH * 2), blk>>>(ka, kb);
    peer_kernel<<<(MM * HH) / 8, blk>>>(u, ev);
    k_gemm_out<<<dim3(DD / 128, MM / 128), blk>>>(Wout);
    ln_kernel<<<MM, blk>>>(lnw, lnb, out);
}

// round 13
// speedup vs baseline: 1.1071x; 1.0291x over previous
#include <cuda_runtime.h>
#include <cuda_bf16.h>
#include <cstdint>
#include <cstddef>

// Problem constants
#define MM   8192      // B*T tokens
#define DD   1024      // model dim
#define HH   8         // heads
#define HD   128       // head dim
#define SS   512       // sub-keys per half
#define KK   16        // top-k

// ---------------------------------------------------------------------------
// Scratch (static device globals)
// ---------------------------------------------------------------------------
__device__ float g_h[(size_t)MM * DD];                 // hidden (fp32, bitwise = R1)
__device__ float g_scores[(size_t)MM * HH * 2 * SS];   // scores (fp32, bitwise = R1)
__device__ float g_merged[(size_t)MM * DD];            // expert output
__device__ float g_proj[(size_t)MM * DD];              // pre-LN projection

// ---------------------------------------------------------------------------
// fp32 NT SGEMM, double-buffered + register prefetch.
// SAME VALUES + SAME FFMA ORDER as R1's sgemm_body -> bitwise-identical C.
// Block tile 128x128, K-chunk 16, 256 threads, 8x8 micro-tile, 1 sync/chunk.
// ---------------------------------------------------------------------------
__device__ __forceinline__ void sgemm_db(const float* __restrict__ A,
                                         const float* __restrict__ B,
                                         float* __restrict__ C,
                                         int Kdim, int lda, int ldb, int ldc)
{
    __shared__ float As[2][16][128];
    __shared__ float Bs[2][16][128];

    const int tid   = threadIdx.x;          // 0..255
    const int tx    = tid & 15;             // n-direction
    const int ty    = tid >> 4;             // m-direction
    const int row_m = blockIdx.y * 128;
    const int col_n = blockIdx.x * 128;

    // loader coordinates: thread covers flat slots tid*2 and tid*2+1
    const int f0  = tid * 2;
    const int r0  = f0 >> 2;                // row 0..127
    const int kq0 = (f0 & 3) * 4;           // k-quad 0,4,8,12
    const int f1  = tid * 2 + 1;
    const int r1  = f1 >> 2;
    const int kq1 = (f1 & 3) * 4;

    const float* Arow0 = A + (size_t)(row_m + r0) * lda + kq0;
    const float* Arow1 = A + (size_t)(row_m + r1) * lda + kq1;
    const float* Brow0 = B + (size_t)(col_n + r0) * ldb + kq0;
    const float* Brow1 = B + (size_t)(col_n + r1) * ldb + kq1;

    float acc[8][8];
#pragma unroll
    for (int i = 0; i < 8; i++)
#pragma unroll
        for (int j = 0; j < 8; j++) acc[i][j] = 0.f;

    // prefetch chunk 0 into registers, stage into buffer 0
    float4 va0 = *(const float4*)(Arow0);
    float4 va1 = *(const float4*)(Arow1);
    float4 vb0 = *(const float4*)(Brow0);
    float4 vb1 = *(const float4*)(Brow1);

    As[0][kq0 + 0][r0] = va0.x; As[0][kq0 + 1][r0] = va0.y;
    As[0][kq0 + 2][r0] = va0.z; As[0][kq0 + 3][r0] = va0.w;
    As[0][kq1 + 0][r1] = va1.x; As[0][kq1 + 1][r1] = va1.y;
    As[0][kq1 + 2][r1] = va1.z; As[0][kq1 + 3][r1] = va1.w;
    Bs[0][kq0 + 0][r0] = vb0.x; Bs[0][kq0 + 1][r0] = vb0.y;
    Bs[0][kq0 + 2][r0] = vb0.z; Bs[0][kq0 + 3][r0] = vb0.w;
    Bs[0][kq1 + 0][r1] = vb1.x; Bs[0][kq1 + 1][r1] = vb1.y;
    Bs[0][kq1 + 2][r1] = vb1.z; Bs[0][kq1 + 3][r1] = vb1.w;
    __syncthreads();

    const int nch = Kdim >> 4;
    for (int c = 0; c < nch; c++) {
        const int cur = c & 1;
        const bool more = (c + 1 < nch);
        if (more) {
            const int k0 = (c + 1) * 16;
            va0 = *(const float4*)(Arow0 + k0);
            va1 = *(const float4*)(Arow1 + k0);
            vb0 = *(const float4*)(Brow0 + k0);
            vb1 = *(const float4*)(Brow1 + k0);
        }

#pragma unroll
        for (int kk = 0; kk < 16; kk++) {
            float a[8], b[8];
#pragma unroll
            for (int i = 0; i < 8; i++) a[i] = As[cur][kk][ty * 8 + i];
#pragma unroll
            for (int j = 0; j < 8; j++) b[j] = Bs[cur][kk][tx * 8 + j];
#pragma unroll
            for (int i = 0; i < 8; i++)
#pragma unroll
                for (int j = 0; j < 8; j++) acc[i][j] += a[i] * b[j];
        }

        if (more) {
            const int nxt = cur ^ 1;
            As[nxt][kq0 + 0][r0] = va0.x; As[nxt][kq0 + 1][r0] = va0.y;
            As[nxt][kq0 + 2][r0] = va0.z; As[nxt][kq0 + 3][r0] = va0.w;
            As[nxt][kq1 + 0][r1] = va1.x; As[nxt][kq1 + 1][r1] = va1.y;
            As[nxt][kq1 + 2][r1] = va1.z; As[nxt][kq1 + 3][r1] = va1.w;
            Bs[nxt][kq0 + 0][r0] = vb0.x; Bs[nxt][kq0 + 1][r0] = vb0.y;
            Bs[nxt][kq0 + 2][r0] = vb0.z; Bs[nxt][kq0 + 3][r0] = vb0.w;
            Bs[nxt][kq1 + 0][r1] = vb1.x; Bs[nxt][kq1 + 1][r1] = vb1.y;
            Bs[nxt][kq1 + 2][r1] = vb1.z; Bs[nxt][kq1 + 3][r1] = vb1.w;
        }
        __syncthreads();
    }

#pragma unroll
    for (int i = 0; i < 8; i++) {
        int m = row_m + ty * 8 + i;
#pragma unroll
        for (int j0 = 0; j0 < 8; j0 += 4) {
            float4 v = make_float4(acc[i][j0], acc[i][j0 + 1], acc[i][j0 + 2], acc[i][j0 + 3]);
            *(float4*)(C + (size_t)m * ldc + col_n + tx * 8 + j0) = v;
        }
    }
}

// GEMM1 (fp32, bitwise = R1): g_h = x @ W_in^T
__global__ void __launch_bounds__(256) k_gemm_in(const float* __restrict__ x,
                                                 const float* __restrict__ Win)
{
    sgemm_db(x, Win, g_h, DD, DD, DD, DD);
}

// Score GEMMs (fp32, bitwise = R1): z = head*2+ab
__global__ void __launch_bounds__(256) k_gemm_scores(const float* __restrict__ ka,
                                                     const float* __restrict__ kb)
{
    const int z = blockIdx.z;
    const int head = z >> 1;
    const int ab = z & 1;
    const float* A = g_h + head * HD;
    const float* B = (ab ? kb : ka) + (size_t)head * SS * HD;
    float* C = g_scores + head * (2 * SS) + ab * SS;
    sgemm_db(A, B, C, HD, DD, HD, HH * 2 * SS);
}

// ---------------------------------------------------------------------------
// tf32x3 mma.sync GEMM — certified fp32-equivalent for GEMM2 (R5/R6 A/B,
// delta 5e-9); in the passing R10 build. Used ONLY for GEMM2.
// ---------------------------------------------------------------------------
__device__ __forceinline__ uint32_t to_tf32(float x) {
    uint32_t h;
    asm("cvt.rna.tf32.f32 %0, %1;" : "=r"(h) : "f"(x));
    return h;
}
__device__ __forceinline__ void split_tf32(float x, uint32_t& hi, uint32_t& lo) {
    hi = to_tf32(x);
    lo = to_tf32(x - __uint_as_float(hi));
}
__device__ __forceinline__ void mma_tf32(float* c, const uint32_t* a, const uint32_t* b) {
    asm volatile(
        "mma.sync.aligned.m16n8k8.row.col.f32.tf32.tf32.f32 "
        "{%0,%1,%2,%3}, {%4,%5,%6,%7}, {%8,%9}, {%0,%1,%2,%3};"
        : "+f"(c[0]), "+f"(c[1]), "+f"(c[2]), "+f"(c[3])
        : "r"(a[0]), "r"(a[1]), "r"(a[2]), "r"(a[3]), "r"(b[0]), "r"(b[1]));
}

#define SMEM_STRIDE 36

__device__ __forceinline__ void gemm_x3(const float* __restrict__ A,
                                        const float* __restrict__ B,
                                        float* __restrict__ C,
                                        int lda, int ldb, int ldc, int Kdim)
{
    __shared__ float As[128][SMEM_STRIDE];
    __shared__ float Bs[128][SMEM_STRIDE];

    const int tid  = threadIdx.x;
    const int lane = tid & 31;
    const int wid  = tid >> 5;
    const int wr   = wid >> 1;
    const int wc   = wid & 1;
    const int row_m = blockIdx.y * 128;
    const int col_n = blockIdx.x * 128;

    const int lr = lane >> 2;
    const int lc = lane & 3;

    float acc[2][8][4];
#pragma unroll
    for (int mt = 0; mt < 2; mt++)
#pragma unroll
        for (int nt = 0; nt < 8; nt++)
#pragma unroll
            for (int i = 0; i < 4; i++) acc[mt][nt][i] = 0.f;

    for (int k0 = 0; k0 < Kdim; k0 += 32) {
        __syncthreads();
#pragma unroll
        for (int i = 0; i < 4; i++) {
            const int f  = tid + i * 256;
            const int r  = f >> 3;
            const int c4 = (f & 7) * 4;
            *(float4*)&As[r][c4] = *(const float4*)(A + (size_t)(row_m + r) * lda + k0 + c4);
            *(float4*)&Bs[r][c4] = *(const float4*)(B + (size_t)(col_n + r) * ldb + k0 + c4);
        }
        __syncthreads();

#pragma unroll
        for (int ks = 0; ks < 4; ks++) {
            const int kk = ks * 8;
            uint32_t ah[2][4], al[2][4];
#pragma unroll
            for (int mt = 0; mt < 2; mt++) {
                const int rbase = 32 * wr + 16 * mt + lr;
                split_tf32(As[rbase    ][kk + lc    ], ah[mt][0], al[mt][0]);
                split_tf32(As[rbase + 8][kk + lc    ], ah[mt][1], al[mt][1]);
                split_tf32(As[rbase    ][kk + lc + 4], ah[mt][2], al[mt][2]);
                split_tf32(As[rbase + 8][kk + lc + 4], ah[mt][3], al[mt][3]);
            }
#pragma unroll
            for (int half = 0; half < 2; half++) {
                uint32_t bh[4][2], bl[4][2];
#pragma unroll
                for (int nt2 = 0; nt2 < 4; nt2++) {
                    const int n = 64 * wc + 8 * (half * 4 + nt2) + lr;
                    split_tf32(Bs[n][kk + lc    ], bh[nt2][0], bl[nt2][0]);
                    split_tf32(Bs[n][kk + lc + 4], bh[nt2][1], bl[nt2][1]);
                }
#pragma unroll
                for (int mt = 0; mt < 2; mt++)
#pragma unroll
                    for (int nt2 = 0; nt2 < 4; nt2++) {
                        float* c = acc[mt][half * 4 + nt2];
                        mma_tf32(c, ah[mt], bh[nt2]);   // hi*hi
                        mma_tf32(c, ah[mt], bl[nt2]);   // hi*lo
                        mma_tf32(c, al[mt], bh[nt2]);   // lo*hi
                    }
            }
        }
    }

#pragma unroll
    for (int mt = 0; mt < 2; mt++) {
        const int row0 = row_m + 32 * wr + 16 * mt + lr;
#pragma unroll
        for (int nt = 0; nt < 8; nt++) {
            const int col0 = col_n + 64 * wc + 8 * nt + 2 * lc;
            *(float2*)(C + (size_t)row0 * ldc + col0) =
                make_float2(acc[mt][nt][0], acc[mt][nt][1]);
            *(float2*)(C + (size_t)(row0 + 8) * ldc + col0) =
                make_float2(acc[mt][nt][2], acc[mt][nt][3]);
        }
    }
}

// GEMM2 (x3, certified): g_proj = g_merged @ W_out^T
__global__ void __launch_bounds__(256, 2) k_gemm_out(const float* __restrict__ Wout)
{
    gemm_x3(g_merged, Wout, g_proj, DD, DD, DD, DD);
}

// ---------------------------------------------------------------------------
// PEER selection + gather kernel — EXACT R1 code (passing).
// ---------------------------------------------------------------------------
#define NEG_INF (-3.402823466e38f)

#define LOCAL_BEST(arr, n, bv, bi)                                   \
    {                                                                \
        bv = NEG_INF; bi = lane;                                     \
        _Pragma("unroll")                                            \
        for (int _j = 0; _j < (n); _j++) {                           \
            if ((arr)[_j] > bv) { bv = (arr)[_j]; bi = _j * 32 + lane; } \
        }                                                            \
    }

#define KILL(arr, n, gi)                                             \
    {                                                                \
        _Pragma("unroll")                                            \
        for (int _j = 0; _j < (n); _j++) {                           \
            if (_j == ((gi) >> 5)) (arr)[_j] = NEG_INF;              \
        }                                                            \
    }

#define WARP_ARGMAX(v, i)                                            \
    {                                                                \
        _Pragma("unroll")                                            \
        for (int _o = 16; _o; _o >>= 1) {                            \
            float _ov = __shfl_xor_sync(0xffffffffu, v, _o);         \
            int   _oi = __shfl_xor_sync(0xffffffffu, i, _o);         \
            if (_ov > v || (_ov == v && _oi < i)) { v = _ov; i = _oi; } \
        }                                                            \
    }

__global__ void __launch_bounds__(256) peer_kernel(const float* __restrict__ u_shared,
                                                   const float* __restrict__ expert_v)
{
    const int lane = threadIdx.x & 31;
    const int wid  = threadIdx.x >> 5;
    const int id   = blockIdx.x * 8 + wid;   // m*H + head
    const int m    = id >> 3;
    const int head = id & 7;

    const float* srow = g_scores + (size_t)id * (2 * SS);

    float sa[16], sb[16];
#pragma unroll
    for (int j = 0; j < 16; j++) sa[j] = srow[j * 32 + lane];
#pragma unroll
    for (int j = 0; j < 16; j++) sb[j] = srow[SS + j * 32 + lane];

    float ta_v = 0.f, tb_v = 0.f;
    int   ta_i = 0,   tb_i = 0;

    for (int k = 0; k < 16; k++) {
        float bv; int bi;
        LOCAL_BEST(sa, 16, bv, bi);
        WARP_ARGMAX(bv, bi);
        if (lane == k) { ta_v = bv; ta_i = bi; }
        if ((bi & 31) == lane) KILL(sa, 16, bi);
    }
    for (int k = 0; k < 16; k++) {
        float bv; int bi;
        LOCAL_BEST(sb, 16, bv, bi);
        WARP_ARGMAX(bv, bi);
        if (lane == k) { tb_v = bv; tb_i = bi; }
        if ((bi & 31) == lane) KILL(sb, 16, bi);
    }

    const int hi = (lane >> 4) & 1;
    const float tbv_mine = __shfl_sync(0xffffffffu, tb_v, lane & 15);
    float pv[8];
#pragma unroll
    for (int j = 0; j < 8; j++)
        pv[j] = __shfl_sync(0xffffffffu, ta_v, 2 * j + hi) + tbv_mine;

    float sel_sc = 0.f; int sel_e = 0;
    for (int k = 0; k < 16; k++) {
        float bv; int bi;
        LOCAL_BEST(pv, 8, bv, bi);
        WARP_ARGMAX(bv, bi);
        int ia = bi >> 4, ib = bi & 15;
        int ei = __shfl_sync(0xffffffffu, ta_i, ia) * SS +
                 __shfl_sync(0xffffffffu, tb_i, ib);
        if (lane == k) { sel_sc = bv; sel_e = ei; }
        if ((bi & 31) == lane) KILL(pv, 8, bi);
    }

    const float mx = __shfl_sync(0xffffffffu, sel_sc, 0);
    float e   = (lane < 16) ? expf(sel_sc - mx) : 0.f;
    float sum = e;
#pragma unroll
    for (int o = 16; o; o >>= 1) sum += __shfl_xor_sync(0xffffffffu, sum, o);
    const float wgt = e / sum;

    float4 acc = make_float4(0.f, 0.f, 0.f, 0.f);
    const float4* ev4 = (const float4*)expert_v;
#pragma unroll
    for (int k = 0; k < 16; k++) {
        float wk = __shfl_sync(0xffffffffu, wgt, k);
        int   ek = __shfl_sync(0xffffffffu, sel_e, k);
        float4 v = ev4[(size_t)ek * 32 + lane];
        acc.x += wk * v.x; acc.y += wk * v.y; acc.z += wk * v.z; acc.w += wk * v.w;
    }

    const float4 hv = ((const float4*)(g_h + (size_t)m * DD + head * HD))[lane];
    const float4 uv = ((const float4*)u_shared)[lane];
    float dot = hv.x * uv.x + hv.y * uv.y + hv.z * uv.z + hv.w * uv.w;
#pragma unroll
    for (int o = 16; o; o >>= 1) dot += __shfl_xor_sync(0xffffffffu, dot, o);
    const float act = 1.f / (1.f + expf(-dot));

    float4 o4 = make_float4(act * acc.x, act * acc.y, act * acc.z, act * acc.w);
    ((float4*)(g_merged + (size_t)m * DD + head * HD))[lane] = o4;
}

// ---------------------------------------------------------------------------
// LayerNorm over D=1024: one block (256 thr) per token — EXACT R1 code
// ---------------------------------------------------------------------------
__device__ __forceinline__ float wsum(float v)
{
#pragma unroll
    for (int o = 16; o; o >>= 1) v += __shfl_xor_sync(0xffffffffu, v, o);
    return v;
}

__global__ void __launch_bounds__(256) ln_kernel(const float* __restrict__ ln_w,
                                                 const float* __restrict__ ln_b,
                                                 float* __restrict__ out)
{
    const int m    = blockIdx.x;
    const int tid  = threadIdx.x;
    const int lane = tid & 31;
    const int wid  = tid >> 5;

    const float4 v = ((const float4*)(g_proj + (size_t)m * DD))[tid];
    __shared__ float red[8];

    float s = v.x + v.y + v.z + v.w;
    s = wsum(s);
    if (lane == 0) red[wid] = s;
    __syncthreads();
    float mu;
    {
        float t = (lane < 8) ? red[lane] : 0.f;
        t = wsum(t);
        mu = t * (1.0f / 1024.0f);
    }
    __syncthreads();

    const float dx = v.x - mu, dy = v.y - mu, dz = v.z - mu, dw = v.w - mu;
    float q = dx * dx + dy * dy + dz * dz + dw * dw;
    q = wsum(q);
    if (lane == 0) red[wid] = q;
    __syncthreads();
    float var;
    {
        float t = (lane < 8) ? red[lane] : 0.f;
        t = wsum(t);
        var = t * (1.0f / 1024.0f);
    }
    const float inv = rsqrtf(var + 1e-5f);

    const float4 w4 = ((const float4*)ln_w)[tid];
    const float4 b4 = ((const float4*)ln_b)[tid];
    float4 o;
    o.x = dx * inv * w4.x + b4.x;
    o.y = dy * inv * w4.y + b4.y;
    o.z = dz * inv * w4.z + b4.z;
    o.w = dw * inv * w4.w + b4.w;
    ((float4*)(out + (size_t)m * DD))[tid] = o;
}

// ---------------------------------------------------------------------------
// Launch pipeline
// ---------------------------------------------------------------------------
extern "C" void kernel_launch(void* const* d_in, const int* in_sizes, int n_in,
                              void* d_out, int out_size)
{
    (void)in_sizes; (void)n_in; (void)out_size;
    const float* x    = (const float*)d_in[0];
    const float* Win  = (const float*)d_in[1];
    const float* ka   = (const float*)d_in[2];
    const float* kb   = (const float*)d_in[3];
    const float* u    = (const float*)d_in[4];
    const float* ev   = (const float*)d_in[5];
    const float* Wout = (const float*)d_in[6];
    const float* lnw  = (const float*)d_in[7];
    const float* lnb  = (const float*)d_in[8];
    float* out = (float*)d_out;

    dim3 blk(256);
    k_gemm_in<<<dim3(DD / 128, MM / 128), blk>>>(x, Win);
    k_gemm_scores<<<dim3(SS / 128, MM / 128, HH * 2), blk>>>(ka, kb);
    peer_kernel<<<(MM * HH) / 8, blk>>>(u, ev);
    k_gemm_out<<<dim3(DD / 128, MM / 128), blk>>>(Wout);
    ln_kernel<<<MM, blk>>>(lnw, lnb, out);
}